// round 8
// baseline (speedup 1.0000x reference)
#include <cuda_runtime.h>
#include <cuda_fp16.h>
#include <math.h>
#include <stdint.h>

// ---------------- problem constants ----------------
#define B_   8
#define HH_  56
#define WW_  56
#define N_   (HH_*WW_)          // 3136
#define C_   512
#define NH_  16
#define HD_  32
#define WS_  7
#define WS2_ 49
#define HID_ 2048
#define TOK_ (B_*N_)            // 25088
#define THREEC_ (3*C_)          // 1536

// ---------------- scratch ----------------
static __device__ __half g_hh  [(size_t)TOK_*C_];
static __device__ __half g_qkvh[(size_t)TOK_*THREEC_];
static __device__ float  g_x1  [(size_t)TOK_*C_];
static __device__ __half g_h2h [(size_t)TOK_*HID_];
static __device__ __half g_h3h [(size_t)TOK_*HID_];
static __device__ __half g_wq  [(size_t)THREEC_*C_];
static __device__ __half g_wf1 [(size_t)HID_*C_];
static __device__ __half g_wf2 [(size_t)C_*HID_];

// ---------------- fp32 -> fp16 conversion ----------------
__global__ __launch_bounds__(256)
void f2h_kernel(const float4* __restrict__ in, __half2* __restrict__ out, int n4) {
    int i = blockIdx.x * 256 + threadIdx.x;
    if (i >= n4) return;
    float4 v = in[i];
    out[2 * i]     = __floats2half2_rn(v.x, v.y);
    out[2 * i + 1] = __floats2half2_rn(v.z, v.w);
}

// ---------------- LayerNorm: warp per row ----------------
__global__ __launch_bounds__(256)
void ln_kernel(const float* __restrict__ x, const float* __restrict__ g,
               const float* __restrict__ b, __half* __restrict__ out) {
    __shared__ float sg[C_], sb[C_];
    const int tid = threadIdx.x;
    sg[tid] = g[tid]; sg[tid + 256] = g[tid + 256];
    sb[tid] = b[tid]; sb[tid + 256] = b[tid + 256];
    __syncthreads();

    const int lane = tid & 31, wid = tid >> 5;
    const long row = (long)blockIdx.x * 8 + wid;
    const float4* xr = (const float4*)(x + row * C_);

    float4 v[4];
    float sum = 0.0f;
    #pragma unroll
    for (int k = 0; k < 4; ++k) {
        v[k] = xr[lane + k * 32];
        sum += v[k].x + v[k].y + v[k].z + v[k].w;
    }
    #pragma unroll
    for (int o = 16; o > 0; o >>= 1) sum += __shfl_xor_sync(0xffffffffu, sum, o);
    float mu = sum * (1.0f / C_);

    float vs = 0.0f;
    #pragma unroll
    for (int k = 0; k < 4; ++k) {
        float dx = v[k].x - mu, dy = v[k].y - mu, dz = v[k].z - mu, dw = v[k].w - mu;
        vs += dx * dx + dy * dy + dz * dz + dw * dw;
    }
    #pragma unroll
    for (int o = 16; o > 0; o >>= 1) vs += __shfl_xor_sync(0xffffffffu, vs, o);
    float inv = rsqrtf(vs * (1.0f / C_) + 1e-5f);

    __half2* orow = (__half2*)(out + row * C_);
    #pragma unroll
    for (int k = 0; k < 4; ++k) {
        int i4 = lane + k * 32, c = i4 * 4;
        float e0 = (v[k].x - mu) * inv * sg[c]     + sb[c];
        float e1 = (v[k].y - mu) * inv * sg[c + 1] + sb[c + 1];
        float e2 = (v[k].z - mu) * inv * sg[c + 2] + sb[c + 2];
        float e3 = (v[k].w - mu) * inv * sg[c + 3] + sb[c + 3];
        orow[i4 * 2]     = __floats2half2_rn(e0, e1);
        orow[i4 * 2 + 1] = __floats2half2_rn(e2, e3);
    }
}

// ---------------- FP16 GEMM: 128x128 CTA, 4 warps 64x64, 4-stage pipeline -----------
#define BM 128
#define BN 128
#define BKH 32
#define LST 40
#define STAGEH ((BM + BN) * LST)
#define NSTG 4
#define GSMEM (NSTG * STAGEH * 2)

__device__ __forceinline__ void cpa16(uint32_t s, const void* g) {
    asm volatile("cp.async.ca.shared.global [%0], [%1], 16;" :: "r"(s), "l"(g));
}
__device__ __forceinline__ void ldsm4(uint32_t* r, uint32_t addr) {
    asm volatile("ldmatrix.sync.aligned.m8n8.x4.shared.b16 {%0,%1,%2,%3}, [%4];"
                 : "=r"(r[0]), "=r"(r[1]), "=r"(r[2]), "=r"(r[3]) : "r"(addr));
}
__device__ __forceinline__ void mma_f16(float* c, const uint32_t* a, const uint32_t* b) {
    asm volatile(
        "mma.sync.aligned.m16n8k16.row.col.f32.f16.f16.f32 "
        "{%0,%1,%2,%3}, {%4,%5,%6,%7}, {%8,%9}, {%0,%1,%2,%3};"
        : "+f"(c[0]), "+f"(c[1]), "+f"(c[2]), "+f"(c[3])
        : "r"(a[0]), "r"(a[1]), "r"(a[2]), "r"(a[3]), "r"(b[0]), "r"(b[1]));
}

template<bool OUT_HALF, bool HAS_RES>
__global__ __launch_bounds__(128, 2)
void gemm_h_kernel(const __half* __restrict__ A, const __half* __restrict__ Bm,
                   const float* __restrict__ bias, const float* __restrict__ res,
                   void* __restrict__ outv, int M, int N, int K) {
    extern __shared__ __half sm[];
    const uint32_t smb = (uint32_t)__cvta_generic_to_shared(sm);
    const int tid = threadIdx.x;
    const int lane = tid & 31, wid = tid >> 5;
    const int wm = wid & 1, wn = wid >> 1;
    const int g8 = lane >> 2, tig = lane & 3;
    const int m0 = blockIdx.y * BM, n0 = blockIdx.x * BN;

    float acc[4][8][4];
    #pragma unroll
    for (int i = 0; i < 4; ++i)
        #pragma unroll
        for (int j = 0; j < 8; ++j)
            #pragma unroll
            for (int t = 0; t < 4; ++t) acc[i][j][t] = 0.0f;

    const int T = K / BKH;
    const int lrow = tid >> 2, lq = tid & 3;

    auto load_stage = [&](int t, int s) {
        const int k0 = t * BKH;
        #pragma unroll
        for (int i = 0; i < 4; ++i) {
            int row = lrow + i * 32;
            uint32_t sa = smb + (uint32_t)(s * STAGEH + row * LST + lq * 8) * 2u;
            cpa16(sa, A + (long)(m0 + row) * K + k0 + lq * 8);
            cpa16(sa + BM * LST * 2u, Bm + (long)(n0 + row) * K + k0 + lq * 8);
        }
    };

    load_stage(0, 0); asm volatile("cp.async.commit_group;");
    load_stage(1, 1); asm volatile("cp.async.commit_group;");
    load_stage(2, 2); asm volatile("cp.async.commit_group;");

    const int a_r = (lane & 15), a_k = (lane >> 4) * 8;
    const int b_r = (lane & 7), b_t = (lane >> 4), b_k = ((lane >> 3) & 1) * 8;

    for (int t = 0; t < T; ++t) {
        const int s = t & 3;
        asm volatile("cp.async.wait_group 2;");
        __syncthreads();
        if (t + 3 < T) load_stage(t + 3, (t + 3) & 3);
        asm volatile("cp.async.commit_group;");

        const uint32_t sA = smb + (uint32_t)(s * STAGEH) * 2u;
        const uint32_t sB = sA + BM * LST * 2u;

        #pragma unroll
        for (int kk = 0; kk < 2; ++kk) {
            const int kb = kk * 16;
            uint32_t a[4][4], b[8][2];
            #pragma unroll
            for (int i = 0; i < 4; ++i)
                ldsm4(a[i], sA + (uint32_t)((wm * 64 + i * 16 + a_r) * LST + kb + a_k) * 2u);
            #pragma unroll
            for (int jp = 0; jp < 4; ++jp) {
                uint32_t r[4];
                ldsm4(r, sB + (uint32_t)((wn * 64 + (jp * 2 + b_t) * 8 + b_r) * LST + kb + b_k) * 2u);
                b[jp * 2][0] = r[0]; b[jp * 2][1] = r[1];
                b[jp * 2 + 1][0] = r[2]; b[jp * 2 + 1][1] = r[3];
            }
            #pragma unroll
            for (int i = 0; i < 4; ++i)
                #pragma unroll
                for (int j = 0; j < 8; ++j) mma_f16(acc[i][j], a[i], b[j]);
        }
    }

    // epilogue
    #pragma unroll
    for (int i = 0; i < 4; ++i) {
        int r = m0 + wm * 64 + i * 16 + g8;
        #pragma unroll
        for (int j = 0; j < 8; ++j) {
            int n = n0 + wn * 64 + j * 8 + tig * 2;
            float b0 = bias[n], b1 = bias[n + 1];
            float v0 = acc[i][j][0] + b0, v1 = acc[i][j][1] + b1;
            float v2 = acc[i][j][2] + b0, v3 = acc[i][j][3] + b1;
            long o0 = (long)r * N + n;
            long o1 = (long)(r + 8) * N + n;
            if (HAS_RES) {
                float2 r0 = *(const float2*)(res + o0);
                float2 r1 = *(const float2*)(res + o1);
                v0 += r0.x; v1 += r0.y; v2 += r1.x; v3 += r1.y;
            }
            if (OUT_HALF) {
                __half* out = (__half*)outv;
                *(__half2*)(out + o0) = __floats2half2_rn(v0, v1);
                *(__half2*)(out + o1) = __floats2half2_rn(v2, v3);
            } else {
                float* out = (float*)outv;
                *(float2*)(out + o0) = make_float2(v0, v1);
                *(float2*)(out + o1) = make_float2(v2, v3);
            }
        }
    }
}

// ---------------- Windowed attention: 3x3 register-tiled QK, float4 AV --------------
__global__ __launch_bounds__(256)
void attn_kernel(const __half* __restrict__ qkv, const float* __restrict__ rpb,
                 const float* __restrict__ x, float* __restrict__ x1) {
    const int head = blockIdx.x & 15;
    const int win  = blockIdx.x >> 4;
    const int b    = win >> 6;
    const int wi   = (win >> 3) & 7;
    const int wj   = win & 7;
    const int tid  = threadIdx.x;

    __shared__ __align__(16) float q[WS2_][HD_ + 1];
    __shared__ __align__(16) float k[WS2_][HD_ + 1];
    __shared__ __align__(16) float v[WS2_][36];
    __shared__ __align__(16) float s[WS2_][WS2_ + 1];

    for (int idx = tid; idx < WS2_ * 16; idx += 256) {
        int p = idx >> 4, d2 = idx & 15;
        int token = (wi * 7 + p / 7) * 56 + (wj * 7 + p % 7);
        long base = ((long)b * N_ + token) * THREEC_ + head * HD_ + 2 * d2;
        float2 fq = __half22float2(*(const __half2*)(qkv + base));
        float2 fk = __half22float2(*(const __half2*)(qkv + base + C_));
        float2 fv = __half22float2(*(const __half2*)(qkv + base + 2 * C_));
        q[p][2 * d2] = fq.x; q[p][2 * d2 + 1] = fq.y;
        k[p][2 * d2] = fk.x; k[p][2 * d2 + 1] = fk.y;
        v[p][2 * d2] = fv.x; v[p][2 * d2 + 1] = fv.y;
    }
    __syncthreads();

    const float scale = 0.17677669529663687f;

    // main 48x48 via 16x16 threads, 3x3 per thread
    {
        const int ib = tid >> 4, jb = tid & 15;
        float acc[3][3];
        #pragma unroll
        for (int r = 0; r < 3; ++r)
            #pragma unroll
            for (int c = 0; c < 3; ++c) acc[r][c] = 0.0f;
        #pragma unroll
        for (int d = 0; d < HD_; ++d) {
            float qa0 = q[ib][d], qa1 = q[ib + 16][d], qa2 = q[ib + 32][d];
            float kb0 = k[jb][d], kb1 = k[jb + 16][d], kb2 = k[jb + 32][d];
            acc[0][0] = fmaf(qa0, kb0, acc[0][0]);
            acc[0][1] = fmaf(qa0, kb1, acc[0][1]);
            acc[0][2] = fmaf(qa0, kb2, acc[0][2]);
            acc[1][0] = fmaf(qa1, kb0, acc[1][0]);
            acc[1][1] = fmaf(qa1, kb1, acc[1][1]);
            acc[1][2] = fmaf(qa1, kb2, acc[1][2]);
            acc[2][0] = fmaf(qa2, kb0, acc[2][0]);
            acc[2][1] = fmaf(qa2, kb1, acc[2][1]);
            acc[2][2] = fmaf(qa2, kb2, acc[2][2]);
        }
        #pragma unroll
        for (int r = 0; r < 3; ++r) {
            int i = ib + r * 16;
            #pragma unroll
            for (int c = 0; c < 3; ++c) {
                int j = jb + c * 16;
                int dpi = (i / 7) - (j / 7) + 6;
                int dpj = (i % 7) - (j % 7) + 6;
                s[i][j] = acc[r][c] * scale + rpb[(dpi * 13 + dpj) * NH_ + head];
            }
        }
    }
    // edges: i=48 row (49) + j=48 col (48) = 97 scores
    if (tid < 97) {
        int i = (tid < 49) ? 48 : (tid - 49);
        int j = (tid < 49) ? tid : 48;
        float acc = 0.0f;
        #pragma unroll
        for (int d = 0; d < HD_; ++d) acc = fmaf(q[i][d], k[j][d], acc);
        int dpi = (i / 7) - (j / 7) + 6;
        int dpj = (i % 7) - (j % 7) + 6;
        s[i][j] = acc * scale + rpb[(dpi * 13 + dpj) * NH_ + head];
    }
    __syncthreads();

    if (tid < WS2_) {
        float mx = -1e30f;
        #pragma unroll
        for (int j = 0; j < WS2_; ++j) mx = fmaxf(mx, s[tid][j]);
        float sum = 0.0f;
        #pragma unroll
        for (int j = 0; j < WS2_; ++j) { float e = __expf(s[tid][j] - mx); s[tid][j] = e; sum += e; }
        float inv = 1.0f / sum;
        #pragma unroll
        for (int j = 0; j < WS2_; ++j) s[tid][j] *= inv;
    }
    __syncthreads();

    // AV: thread -> (i, d4), float4 over head dim
    for (int idx = tid; idx < WS2_ * 8; idx += 256) {
        int i = idx >> 3, d4 = (idx & 7) * 4;
        float4 a = make_float4(0.f, 0.f, 0.f, 0.f);
        #pragma unroll
        for (int j = 0; j < WS2_; ++j) {
            float sv = s[i][j];
            float4 vv = *(const float4*)&v[j][d4];
            a.x = fmaf(sv, vv.x, a.x);
            a.y = fmaf(sv, vv.y, a.y);
            a.z = fmaf(sv, vv.z, a.z);
            a.w = fmaf(sv, vv.w, a.w);
        }
        int token = (wi * 7 + i / 7) * 56 + (wj * 7 + i % 7);
        long o = ((long)b * N_ + token) * C_ + head * HD_ + d4;
        float4 xv = *(const float4*)(x + o);
        a.x += xv.x; a.y += xv.y; a.z += xv.z; a.w += xv.w;
        *(float4*)(x1 + o) = a;
    }
}

// ---------------- depthwise 3x3 + GELU: row-sweep ----------------
__global__ __launch_bounds__(256)
void dwconv_gelu_kernel(const __half2* __restrict__ h2, const float* __restrict__ w,
                        const float* __restrict__ bias, __half2* __restrict__ out) {
    __shared__ float ws[512 * 9];
    const int bid = blockIdx.x;
    const int chunk = bid & 3;
    const int hrow = (bid >> 2) % 56;
    const int bb = (bid >> 2) / 56;
    const int cp = chunk * 256 + threadIdx.x;

    for (int q = threadIdx.x; q < 512 * 9; q += 256)
        ws[q] = w[(long)(chunk * 512) * 9 + q];
    __syncthreads();

    const float* w0 = &ws[(2 * threadIdx.x) * 9];
    const float* w1 = w0 + 9;
    const int c = cp * 2;
    const float bi0 = bias[c], bi1 = bias[c + 1];

    const bool up = (hrow > 0), dn = (hrow < 55);
    const long rbase = (((long)bb * 56 + hrow) * 56) * 1024 + cp;
    const long rup = rbase - 56 * 1024, rdn = rbase + 56 * 1024;

    float2 col[3][3];
    #pragma unroll
    for (int j = 0; j < 3; ++j)
        #pragma unroll
        for (int dy = 0; dy < 3; ++dy) col[j][dy] = make_float2(0.f, 0.f);

    col[1][0] = up ? __half22float2(h2[rup]) : make_float2(0.f, 0.f);
    col[1][1] = __half22float2(h2[rbase]);
    col[1][2] = dn ? __half22float2(h2[rdn]) : make_float2(0.f, 0.f);

    for (int wcol = 0; wcol < 56; ++wcol) {
        if (wcol + 1 < 56) {
            long o = (long)(wcol + 1) * 1024;
            col[2][0] = up ? __half22float2(h2[rup + o]) : make_float2(0.f, 0.f);
            col[2][1] = __half22float2(h2[rbase + o]);
            col[2][2] = dn ? __half22float2(h2[rdn + o]) : make_float2(0.f, 0.f);
        } else {
            col[2][0] = col[2][1] = col[2][2] = make_float2(0.f, 0.f);
        }

        float a0 = bi0, a1 = bi1;
        #pragma unroll
        for (int dy = 0; dy < 3; ++dy) {
            #pragma unroll
            for (int dx = 0; dx < 3; ++dx) {
                float2 vv = col[dx][dy];
                a0 = fmaf(vv.x, w0[dy * 3 + dx], a0);
                a1 = fmaf(vv.y, w1[dy * 3 + dx], a1);
            }
        }
        float g0 = 0.5f * a0 * (1.0f + erff(a0 * 0.70710678118654752f));
        float g1 = 0.5f * a1 * (1.0f + erff(a1 * 0.70710678118654752f));
        out[rbase + (long)wcol * 1024] = __floats2half2_rn(g0, g1);

        #pragma unroll
        for (int dy = 0; dy < 3; ++dy) { col[0][dy] = col[1][dy]; col[1][dy] = col[2][dy]; }
    }
}

// ---------------- launch ----------------
extern "C" void kernel_launch(void* const* d_in, const int* in_sizes, int n_in,
                              void* d_out, int out_size) {
    const float* x       = (const float*)d_in[0];
    const float* norm1_g = (const float*)d_in[3];
    const float* norm1_b = (const float*)d_in[4];
    const float* norm2_g = (const float*)d_in[5];
    const float* norm2_b = (const float*)d_in[6];
    const float* qkv_w   = (const float*)d_in[7];
    const float* qkv_b   = (const float*)d_in[8];
    const float* rpb     = (const float*)d_in[9];
    const float* fc1_w   = (const float*)d_in[10];
    const float* fc1_b   = (const float*)d_in[11];
    const float* dw_w    = (const float*)d_in[12];
    const float* dw_b    = (const float*)d_in[13];
    const float* fc2_w   = (const float*)d_in[14];
    const float* fc2_b   = (const float*)d_in[15];
    float* out = (float*)d_out;

    __half *p_hh, *p_qkvh, *p_h2h, *p_h3h, *p_wq, *p_wf1, *p_wf2;
    float *p_x1;
    cudaGetSymbolAddress((void**)&p_hh,   g_hh);
    cudaGetSymbolAddress((void**)&p_qkvh, g_qkvh);
    cudaGetSymbolAddress((void**)&p_x1,   g_x1);
    cudaGetSymbolAddress((void**)&p_h2h,  g_h2h);
    cudaGetSymbolAddress((void**)&p_h3h,  g_h3h);
    cudaGetSymbolAddress((void**)&p_wq,   g_wq);
    cudaGetSymbolAddress((void**)&p_wf1,  g_wf1);
    cudaGetSymbolAddress((void**)&p_wf2,  g_wf2);

    cudaFuncSetAttribute(gemm_h_kernel<true, false>,
                         cudaFuncAttributeMaxDynamicSharedMemorySize, GSMEM);
    cudaFuncSetAttribute(gemm_h_kernel<false, true>,
                         cudaFuncAttributeMaxDynamicSharedMemorySize, GSMEM);

    // 0) weight conversions
    f2h_kernel<<<(THREEC_ * C_ / 4 + 255) / 256, 256>>>((const float4*)qkv_w, (__half2*)p_wq, THREEC_ * C_ / 4);
    f2h_kernel<<<(HID_ * C_ / 4 + 255) / 256, 256>>>((const float4*)fc1_w, (__half2*)p_wf1, HID_ * C_ / 4);
    f2h_kernel<<<(C_ * HID_ / 4 + 255) / 256, 256>>>((const float4*)fc2_w, (__half2*)p_wf2, C_ * HID_ / 4);

    // 1) LN1
    ln_kernel<<<TOK_ / 8, 256>>>(x, norm1_g, norm1_b, p_hh);
    // 2) QKV GEMM
    gemm_h_kernel<true, false><<<dim3(THREEC_ / BN, TOK_ / BM), 128, GSMEM>>>(
        p_hh, p_wq, qkv_b, nullptr, p_qkvh, TOK_, THREEC_, C_);
    // 3) windowed attention + residual
    attn_kernel<<<B_ * 64 * NH_, 256>>>(p_qkvh, rpb, x, p_x1);
    // 4) LN2
    ln_kernel<<<TOK_ / 8, 256>>>(p_x1, norm2_g, norm2_b, p_hh);
    // 5) fc1 GEMM
    gemm_h_kernel<true, false><<<dim3(HID_ / BN, TOK_ / BM), 128, GSMEM>>>(
        p_hh, p_wf1, fc1_b, nullptr, p_h2h, TOK_, HID_, C_);
    // 6) depthwise conv + GELU
    dwconv_gelu_kernel<<<B_ * HH_ * 4, 256>>>(
        (const __half2*)p_h2h, dw_w, dw_b, (__half2*)p_h3h);
    // 7) fc2 GEMM + residual -> out
    gemm_h_kernel<false, true><<<dim3(C_ / BN, TOK_ / BM), 128, GSMEM>>>(
        p_h3h, p_wf2, fc2_b, p_x1, out, TOK_, C_, HID_);
}

// round 9
// speedup vs baseline: 1.0056x; 1.0056x over previous
#include <cuda_runtime.h>
#include <cuda_fp16.h>
#include <math.h>
#include <stdint.h>

// ---------------- problem constants ----------------
#define B_   8
#define HH_  56
#define WW_  56
#define N_   (HH_*WW_)          // 3136
#define C_   512
#define NH_  16
#define HD_  32
#define WS_  7
#define WS2_ 49
#define HID_ 2048
#define TOK_ (B_*N_)            // 25088
#define THREEC_ (3*C_)          // 1536

// ---------------- scratch ----------------
static __device__ __half g_hh  [(size_t)TOK_*C_];
static __device__ __half g_qkvh[(size_t)TOK_*THREEC_];
static __device__ float  g_x1  [(size_t)TOK_*C_];
static __device__ __half g_h2h [(size_t)TOK_*HID_];
static __device__ __half g_h3h [(size_t)TOK_*HID_];
static __device__ __half g_wq  [(size_t)THREEC_*C_];
static __device__ __half g_wf1 [(size_t)HID_*C_];
static __device__ __half g_wf2 [(size_t)C_*HID_];

// ---------------- fp32 -> fp16 conversion ----------------
__global__ __launch_bounds__(256)
void f2h_kernel(const float4* __restrict__ in, __half2* __restrict__ out, int n4) {
    int i = blockIdx.x * 256 + threadIdx.x;
    if (i >= n4) return;
    float4 v = in[i];
    out[2 * i]     = __floats2half2_rn(v.x, v.y);
    out[2 * i + 1] = __floats2half2_rn(v.z, v.w);
}

// ---------------- LayerNorm: warp per row ----------------
__global__ __launch_bounds__(256)
void ln_kernel(const float* __restrict__ x, const float* __restrict__ g,
               const float* __restrict__ b, __half* __restrict__ out) {
    __shared__ float sg[C_], sb[C_];
    const int tid = threadIdx.x;
    sg[tid] = g[tid]; sg[tid + 256] = g[tid + 256];
    sb[tid] = b[tid]; sb[tid + 256] = b[tid + 256];
    __syncthreads();

    const int lane = tid & 31, wid = tid >> 5;
    const long row = (long)blockIdx.x * 8 + wid;
    const float4* xr = (const float4*)(x + row * C_);

    float4 v[4];
    float sum = 0.0f;
    #pragma unroll
    for (int k = 0; k < 4; ++k) {
        v[k] = xr[lane + k * 32];
        sum += v[k].x + v[k].y + v[k].z + v[k].w;
    }
    #pragma unroll
    for (int o = 16; o > 0; o >>= 1) sum += __shfl_xor_sync(0xffffffffu, sum, o);
    float mu = sum * (1.0f / C_);

    float vs = 0.0f;
    #pragma unroll
    for (int k = 0; k < 4; ++k) {
        float dx = v[k].x - mu, dy = v[k].y - mu, dz = v[k].z - mu, dw = v[k].w - mu;
        vs += dx * dx + dy * dy + dz * dz + dw * dw;
    }
    #pragma unroll
    for (int o = 16; o > 0; o >>= 1) vs += __shfl_xor_sync(0xffffffffu, vs, o);
    float inv = rsqrtf(vs * (1.0f / C_) + 1e-5f);

    __half2* orow = (__half2*)(out + row * C_);
    #pragma unroll
    for (int k = 0; k < 4; ++k) {
        int i4 = lane + k * 32, c = i4 * 4;
        float e0 = (v[k].x - mu) * inv * sg[c]     + sb[c];
        float e1 = (v[k].y - mu) * inv * sg[c + 1] + sb[c + 1];
        float e2 = (v[k].z - mu) * inv * sg[c + 2] + sb[c + 2];
        float e3 = (v[k].w - mu) * inv * sg[c + 3] + sb[c + 3];
        orow[i4 * 2]     = __floats2half2_rn(e0, e1);
        orow[i4 * 2 + 1] = __floats2half2_rn(e2, e3);
    }
}

// ---------------- FP16 GEMM: 128x128 CTA, 4 warps 64x64, 3-stage (R6 proven) --------
#define BM 128
#define BN 128
#define BKH 32
#define LST 40
#define STAGEH ((BM + BN) * LST)
#define GSMEM (3 * STAGEH * 2)

__device__ __forceinline__ void cpa16(uint32_t s, const void* g) {
    asm volatile("cp.async.ca.shared.global [%0], [%1], 16;" :: "r"(s), "l"(g));
}
__device__ __forceinline__ void ldsm4(uint32_t* r, uint32_t addr) {
    asm volatile("ldmatrix.sync.aligned.m8n8.x4.shared.b16 {%0,%1,%2,%3}, [%4];"
                 : "=r"(r[0]), "=r"(r[1]), "=r"(r[2]), "=r"(r[3]) : "r"(addr));
}
__device__ __forceinline__ void mma_f16(float* c, const uint32_t* a, const uint32_t* b) {
    asm volatile(
        "mma.sync.aligned.m16n8k16.row.col.f32.f16.f16.f32 "
        "{%0,%1,%2,%3}, {%4,%5,%6,%7}, {%8,%9}, {%0,%1,%2,%3};"
        : "+f"(c[0]), "+f"(c[1]), "+f"(c[2]), "+f"(c[3])
        : "r"(a[0]), "r"(a[1]), "r"(a[2]), "r"(a[3]), "r"(b[0]), "r"(b[1]));
}

template<bool OUT_HALF, bool HAS_RES>
__global__ __launch_bounds__(128, 2)
void gemm_h_kernel(const __half* __restrict__ A, const __half* __restrict__ Bm,
                   const float* __restrict__ bias, const float* __restrict__ res,
                   void* __restrict__ outv, int M, int N, int K) {
    extern __shared__ __half sm[];
    const uint32_t smb = (uint32_t)__cvta_generic_to_shared(sm);
    const int tid = threadIdx.x;
    const int lane = tid & 31, wid = tid >> 5;
    const int wm = wid & 1, wn = wid >> 1;
    const int g8 = lane >> 2, tig = lane & 3;
    const int m0 = blockIdx.y * BM, n0 = blockIdx.x * BN;

    float acc[4][8][4];
    #pragma unroll
    for (int i = 0; i < 4; ++i)
        #pragma unroll
        for (int j = 0; j < 8; ++j)
            #pragma unroll
            for (int t = 0; t < 4; ++t) acc[i][j][t] = 0.0f;

    const int T = K / BKH;
    const int lrow = tid >> 2, lq = tid & 3;

    auto load_stage = [&](int t, int s) {
        const int k0 = t * BKH;
        #pragma unroll
        for (int i = 0; i < 4; ++i) {
            int row = lrow + i * 32;
            uint32_t sa = smb + (uint32_t)(s * STAGEH + row * LST + lq * 8) * 2u;
            cpa16(sa, A + (long)(m0 + row) * K + k0 + lq * 8);
            cpa16(sa + BM * LST * 2u, Bm + (long)(n0 + row) * K + k0 + lq * 8);
        }
    };

    load_stage(0, 0);
    asm volatile("cp.async.commit_group;");
    if (T > 1) { load_stage(1, 1); asm volatile("cp.async.commit_group;"); }

    const int a_r = (lane & 15), a_k = (lane >> 4) * 8;
    const int b_r = (lane & 7), b_t = (lane >> 4), b_k = ((lane >> 3) & 1) * 8;

    for (int t = 0; t < T; ++t) {
        const int s = t % 3;
        if (t + 2 < T) {
            load_stage(t + 2, (t + 2) % 3);
            asm volatile("cp.async.commit_group;");
            asm volatile("cp.async.wait_group 2;");
        } else if (t + 1 < T) {
            asm volatile("cp.async.wait_group 1;");
        } else {
            asm volatile("cp.async.wait_group 0;");
        }
        __syncthreads();

        const uint32_t sA = smb + (uint32_t)(s * STAGEH) * 2u;
        const uint32_t sB = sA + BM * LST * 2u;

        #pragma unroll
        for (int kk = 0; kk < 2; ++kk) {
            const int kb = kk * 16;
            uint32_t a[4][4], b[8][2];
            #pragma unroll
            for (int i = 0; i < 4; ++i)
                ldsm4(a[i], sA + (uint32_t)((wm * 64 + i * 16 + a_r) * LST + kb + a_k) * 2u);
            #pragma unroll
            for (int jp = 0; jp < 4; ++jp) {
                uint32_t r[4];
                ldsm4(r, sB + (uint32_t)((wn * 64 + (jp * 2 + b_t) * 8 + b_r) * LST + kb + b_k) * 2u);
                b[jp * 2][0] = r[0]; b[jp * 2][1] = r[1];
                b[jp * 2 + 1][0] = r[2]; b[jp * 2 + 1][1] = r[3];
            }
            #pragma unroll
            for (int i = 0; i < 4; ++i)
                #pragma unroll
                for (int j = 0; j < 8; ++j) mma_f16(acc[i][j], a[i], b[j]);
        }
        __syncthreads();
    }

    // epilogue
    #pragma unroll
    for (int i = 0; i < 4; ++i) {
        int r = m0 + wm * 64 + i * 16 + g8;
        #pragma unroll
        for (int j = 0; j < 8; ++j) {
            int n = n0 + wn * 64 + j * 8 + tig * 2;
            float b0 = bias[n], b1 = bias[n + 1];
            float v0 = acc[i][j][0] + b0, v1 = acc[i][j][1] + b1;
            float v2 = acc[i][j][2] + b0, v3 = acc[i][j][3] + b1;
            long o0 = (long)r * N + n;
            long o1 = (long)(r + 8) * N + n;
            if (HAS_RES) {
                float2 r0 = *(const float2*)(res + o0);
                float2 r1 = *(const float2*)(res + o1);
                v0 += r0.x; v1 += r0.y; v2 += r1.x; v3 += r1.y;
            }
            if (OUT_HALF) {
                __half* out = (__half*)outv;
                *(__half2*)(out + o0) = __floats2half2_rn(v0, v1);
                *(__half2*)(out + o1) = __floats2half2_rn(v2, v3);
            } else {
                float* out = (float*)outv;
                *(float2*)(out + o0) = make_float2(v0, v1);
                *(float2*)(out + o1) = make_float2(v2, v3);
            }
        }
    }
}

// ---------------- Windowed attention: 3x3 register-tiled QK, float4 AV --------------
__global__ __launch_bounds__(256)
void attn_kernel(const __half* __restrict__ qkv, const float* __restrict__ rpb,
                 const float* __restrict__ x, float* __restrict__ x1) {
    const int head = blockIdx.x & 15;
    const int win  = blockIdx.x >> 4;
    const int b    = win >> 6;
    const int wi   = (win >> 3) & 7;
    const int wj   = win & 7;
    const int tid  = threadIdx.x;

    __shared__ __align__(16) float q[WS2_][HD_ + 1];
    __shared__ __align__(16) float k[WS2_][HD_ + 1];
    __shared__ __align__(16) float v[WS2_][36];
    __shared__ __align__(16) float s[WS2_][WS2_ + 1];

    for (int idx = tid; idx < WS2_ * 16; idx += 256) {
        int p = idx >> 4, d2 = idx & 15;
        int token = (wi * 7 + p / 7) * 56 + (wj * 7 + p % 7);
        long base = ((long)b * N_ + token) * THREEC_ + head * HD_ + 2 * d2;
        float2 fq = __half22float2(*(const __half2*)(qkv + base));
        float2 fk = __half22float2(*(const __half2*)(qkv + base + C_));
        float2 fv = __half22float2(*(const __half2*)(qkv + base + 2 * C_));
        q[p][2 * d2] = fq.x; q[p][2 * d2 + 1] = fq.y;
        k[p][2 * d2] = fk.x; k[p][2 * d2 + 1] = fk.y;
        v[p][2 * d2] = fv.x; v[p][2 * d2 + 1] = fv.y;
    }
    __syncthreads();

    const float scale = 0.17677669529663687f;

    // main 48x48 via 16x16 threads, 3x3 per thread
    {
        const int ib = tid >> 4, jb = tid & 15;
        float acc[3][3];
        #pragma unroll
        for (int r = 0; r < 3; ++r)
            #pragma unroll
            for (int c = 0; c < 3; ++c) acc[r][c] = 0.0f;
        #pragma unroll
        for (int d = 0; d < HD_; ++d) {
            float qa0 = q[ib][d], qa1 = q[ib + 16][d], qa2 = q[ib + 32][d];
            float kb0 = k[jb][d], kb1 = k[jb + 16][d], kb2 = k[jb + 32][d];
            acc[0][0] = fmaf(qa0, kb0, acc[0][0]);
            acc[0][1] = fmaf(qa0, kb1, acc[0][1]);
            acc[0][2] = fmaf(qa0, kb2, acc[0][2]);
            acc[1][0] = fmaf(qa1, kb0, acc[1][0]);
            acc[1][1] = fmaf(qa1, kb1, acc[1][1]);
            acc[1][2] = fmaf(qa1, kb2, acc[1][2]);
            acc[2][0] = fmaf(qa2, kb0, acc[2][0]);
            acc[2][1] = fmaf(qa2, kb1, acc[2][1]);
            acc[2][2] = fmaf(qa2, kb2, acc[2][2]);
        }
        #pragma unroll
        for (int r = 0; r < 3; ++r) {
            int i = ib + r * 16;
            #pragma unroll
            for (int c = 0; c < 3; ++c) {
                int j = jb + c * 16;
                int dpi = (i / 7) - (j / 7) + 6;
                int dpj = (i % 7) - (j % 7) + 6;
                s[i][j] = acc[r][c] * scale + rpb[(dpi * 13 + dpj) * NH_ + head];
            }
        }
    }
    // edges: i=48 row (49) + j=48 col (48) = 97 scores
    if (tid < 97) {
        int i = (tid < 49) ? 48 : (tid - 49);
        int j = (tid < 49) ? tid : 48;
        float acc = 0.0f;
        #pragma unroll
        for (int d = 0; d < HD_; ++d) acc = fmaf(q[i][d], k[j][d], acc);
        int dpi = (i / 7) - (j / 7) + 6;
        int dpj = (i % 7) - (j % 7) + 6;
        s[i][j] = acc * scale + rpb[(dpi * 13 + dpj) * NH_ + head];
    }
    __syncthreads();

    if (tid < WS2_) {
        float mx = -1e30f;
        #pragma unroll
        for (int j = 0; j < WS2_; ++j) mx = fmaxf(mx, s[tid][j]);
        float sum = 0.0f;
        #pragma unroll
        for (int j = 0; j < WS2_; ++j) { float e = __expf(s[tid][j] - mx); s[tid][j] = e; sum += e; }
        float inv = 1.0f / sum;
        #pragma unroll
        for (int j = 0; j < WS2_; ++j) s[tid][j] *= inv;
    }
    __syncthreads();

    // AV: thread -> (i, d4), float4 over head dim
    for (int idx = tid; idx < WS2_ * 8; idx += 256) {
        int i = idx >> 3, d4 = (idx & 7) * 4;
        float4 a = make_float4(0.f, 0.f, 0.f, 0.f);
        #pragma unroll
        for (int j = 0; j < WS2_; ++j) {
            float sv = s[i][j];
            float4 vv = *(const float4*)&v[j][d4];
            a.x = fmaf(sv, vv.x, a.x);
            a.y = fmaf(sv, vv.y, a.y);
            a.z = fmaf(sv, vv.z, a.z);
            a.w = fmaf(sv, vv.w, a.w);
        }
        int token = (wi * 7 + i / 7) * 56 + (wj * 7 + i % 7);
        long o = ((long)b * N_ + token) * C_ + head * HD_ + d4;
        float4 xv = *(const float4*)(x + o);
        a.x += xv.x; a.y += xv.y; a.z += xv.z; a.w += xv.w;
        *(float4*)(x1 + o) = a;
    }
}

// ---------------- depthwise 3x3 + GELU: row-sweep ----------------
__global__ __launch_bounds__(256)
void dwconv_gelu_kernel(const __half2* __restrict__ h2, const float* __restrict__ w,
                        const float* __restrict__ bias, __half2* __restrict__ out) {
    __shared__ float ws[512 * 9];
    const int bid = blockIdx.x;
    const int chunk = bid & 3;
    const int hrow = (bid >> 2) % 56;
    const int bb = (bid >> 2) / 56;
    const int cp = chunk * 256 + threadIdx.x;

    for (int q = threadIdx.x; q < 512 * 9; q += 256)
        ws[q] = w[(long)(chunk * 512) * 9 + q];
    __syncthreads();

    const float* w0 = &ws[(2 * threadIdx.x) * 9];
    const float* w1 = w0 + 9;
    const int c = cp * 2;
    const float bi0 = bias[c], bi1 = bias[c + 1];

    const bool up = (hrow > 0), dn = (hrow < 55);
    const long rbase = (((long)bb * 56 + hrow) * 56) * 1024 + cp;
    const long rup = rbase - 56 * 1024, rdn = rbase + 56 * 1024;

    float2 col[3][3];
    #pragma unroll
    for (int j = 0; j < 3; ++j)
        #pragma unroll
        for (int dy = 0; dy < 3; ++dy) col[j][dy] = make_float2(0.f, 0.f);

    col[1][0] = up ? __half22float2(h2[rup]) : make_float2(0.f, 0.f);
    col[1][1] = __half22float2(h2[rbase]);
    col[1][2] = dn ? __half22float2(h2[rdn]) : make_float2(0.f, 0.f);

    for (int wcol = 0; wcol < 56; ++wcol) {
        if (wcol + 1 < 56) {
            long o = (long)(wcol + 1) * 1024;
            col[2][0] = up ? __half22float2(h2[rup + o]) : make_float2(0.f, 0.f);
            col[2][1] = __half22float2(h2[rbase + o]);
            col[2][2] = dn ? __half22float2(h2[rdn + o]) : make_float2(0.f, 0.f);
        } else {
            col[2][0] = col[2][1] = col[2][2] = make_float2(0.f, 0.f);
        }

        float a0 = bi0, a1 = bi1;
        #pragma unroll
        for (int dy = 0; dy < 3; ++dy) {
            #pragma unroll
            for (int dx = 0; dx < 3; ++dx) {
                float2 vv = col[dx][dy];
                a0 = fmaf(vv.x, w0[dy * 3 + dx], a0);
                a1 = fmaf(vv.y, w1[dy * 3 + dx], a1);
            }
        }
        float g0 = 0.5f * a0 * (1.0f + erff(a0 * 0.70710678118654752f));
        float g1 = 0.5f * a1 * (1.0f + erff(a1 * 0.70710678118654752f));
        out[rbase + (long)wcol * 1024] = __floats2half2_rn(g0, g1);

        #pragma unroll
        for (int dy = 0; dy < 3; ++dy) { col[0][dy] = col[1][dy]; col[1][dy] = col[2][dy]; }
    }
}

// ---------------- launch ----------------
extern "C" void kernel_launch(void* const* d_in, const int* in_sizes, int n_in,
                              void* d_out, int out_size) {
    const float* x       = (const float*)d_in[0];
    const float* norm1_g = (const float*)d_in[3];
    const float* norm1_b = (const float*)d_in[4];
    const float* norm2_g = (const float*)d_in[5];
    const float* norm2_b = (const float*)d_in[6];
    const float* qkv_w   = (const float*)d_in[7];
    const float* qkv_b   = (const float*)d_in[8];
    const float* rpb     = (const float*)d_in[9];
    const float* fc1_w   = (const float*)d_in[10];
    const float* fc1_b   = (const float*)d_in[11];
    const float* dw_w    = (const float*)d_in[12];
    const float* dw_b    = (const float*)d_in[13];
    const float* fc2_w   = (const float*)d_in[14];
    const float* fc2_b   = (const float*)d_in[15];
    float* out = (float*)d_out;

    __half *p_hh, *p_qkvh, *p_h2h, *p_h3h, *p_wq, *p_wf1, *p_wf2;
    float *p_x1;
    cudaGetSymbolAddress((void**)&p_hh,   g_hh);
    cudaGetSymbolAddress((void**)&p_qkvh, g_qkvh);
    cudaGetSymbolAddress((void**)&p_x1,   g_x1);
    cudaGetSymbolAddress((void**)&p_h2h,  g_h2h);
    cudaGetSymbolAddress((void**)&p_h3h,  g_h3h);
    cudaGetSymbolAddress((void**)&p_wq,   g_wq);
    cudaGetSymbolAddress((void**)&p_wf1,  g_wf1);
    cudaGetSymbolAddress((void**)&p_wf2,  g_wf2);

    cudaFuncSetAttribute(gemm_h_kernel<true, false>,
                         cudaFuncAttributeMaxDynamicSharedMemorySize, GSMEM);
    cudaFuncSetAttribute(gemm_h_kernel<false, true>,
                         cudaFuncAttributeMaxDynamicSharedMemorySize, GSMEM);

    // 0) weight conversions
    f2h_kernel<<<(THREEC_ * C_ / 4 + 255) / 256, 256>>>((const float4*)qkv_w, (__half2*)p_wq, THREEC_ * C_ / 4);
    f2h_kernel<<<(HID_ * C_ / 4 + 255) / 256, 256>>>((const float4*)fc1_w, (__half2*)p_wf1, HID_ * C_ / 4);
    f2h_kernel<<<(C_ * HID_ / 4 + 255) / 256, 256>>>((const float4*)fc2_w, (__half2*)p_wf2, C_ * HID_ / 4);

    // 1) LN1
    ln_kernel<<<TOK_ / 8, 256>>>(x, norm1_g, norm1_b, p_hh);
    // 2) QKV GEMM
    gemm_h_kernel<true, false><<<dim3(THREEC_ / BN, TOK_ / BM), 128, GSMEM>>>(
        p_hh, p_wq, qkv_b, nullptr, p_qkvh, TOK_, THREEC_, C_);
    // 3) windowed attention + residual
    attn_kernel<<<B_ * 64 * NH_, 256>>>(p_qkvh, rpb, x, p_x1);
    // 4) LN2
    ln_kernel<<<TOK_ / 8, 256>>>(p_x1, norm2_g, norm2_b, p_hh);
    // 5) fc1 GEMM
    gemm_h_kernel<true, false><<<dim3(HID_ / BN, TOK_ / BM), 128, GSMEM>>>(
        p_hh, p_wf1, fc1_b, nullptr, p_h2h, TOK_, HID_, C_);
    // 6) depthwise conv + GELU
    dwconv_gelu_kernel<<<B_ * HH_ * 4, 256>>>(
        (const __half2*)p_h2h, dw_w, dw_b, (__half2*)p_h3h);
    // 7) fc2 GEMM + residual -> out
    gemm_h_kernel<false, true><<<dim3(C_ / BN, TOK_ / BM), 128, GSMEM>>>(
        p_h3h, p_wf2, fc2_b, p_x1, out, TOK_, C_, HID_);
}